// round 2
// baseline (speedup 1.0000x reference)
#include <cuda_runtime.h>
#include <cuda_bf16.h>

#define IMG 256
#define TILE 32
#define HALO 3
#define SW (TILE + 2 * HALO)      // 38
#define SPITCH 40                 // padded pitch, avoids bank conflicts

__global__ __launch_bounds__(256, 4)
void AdaptiveGaussianFilter_66675072303489_kernel(
    const float* __restrict__ x,
    const float* __restrict__ sigma,
    float* __restrict__ out)
{
    __shared__ float sm[SW][SPITCH];

    const int ch = blockIdx.z;               // 0..47 (batch*channel)
    const int x0 = blockIdx.x * TILE;
    const int y0 = blockIdx.y * TILE;

    const float* xc = x     + (size_t)ch * IMG * IMG;
    const float* sc = sigma + (size_t)ch * IMG * IMG;
    float*       oc = out   + (size_t)ch * IMG * IMG;

    const int tid = threadIdx.y * 32 + threadIdx.x;
    const int lx  = threadIdx.x;
    const int ly0 = threadIdx.y * 4;

    // ---- Hoisted per-pixel weight chains: 4 independent ILP streams ----
    // Issue the 4 sigma loads first so DRAM latency overlaps the smem fill.
    float tv[4];
    #pragma unroll
    for (int k = 0; k < 4; k++) {
        float s = sc[(y0 + ly0 + k) * IMG + (x0 + lx)];
        tv[k] = __expf(-0.5f * s * s);
    }
    float t4v[4], t9v[4], inv[4];
    #pragma unroll
    for (int k = 0; k < 4; k++) {
        float t2 = tv[k] * tv[k];
        t4v[k] = t2 * t2;
        t9v[k] = t4v[k] * t4v[k] * tv[k];
        float S = fmaf(2.0f, tv[k] + t4v[k] + t9v[k], 1.0f);
        inv[k] = __fdividef(1.0f, S * S);
    }

    // ---- Cooperative load of 38x38 halo tile with reflect padding ----
    #pragma unroll
    for (int i = tid; i < SW * SW; i += 256) {
        int sy = i / SW;
        int sx = i - sy * SW;
        int gy = y0 + sy - HALO;
        int gx = x0 + sx - HALO;
        gy = (gy < 0) ? -gy : ((gy > IMG - 1) ? 2 * (IMG - 1) - gy : gy);
        gx = (gx < 0) ? -gx : ((gx > IMG - 1) ? 2 * (IMG - 1) - gx : gx);
        sm[sy][sx] = xc[gy * IMG + gx];
    }
    __syncthreads();

    // ---- Rolling window of t-independent row quartets (m, a, b, c) ----
    // m = w3, a = w2+w4, b = w1+w5, c = w0+w6  (computed once per row)
    float m[7], a[7], b[7], c[7];
    #pragma unroll
    for (int i = 0; i < 7; i++) {
        const float* row = &sm[ly0 + i][lx];
        m[i] = row[3];
        a[i] = row[2] + row[4];
        b[i] = row[1] + row[5];
        c[i] = row[0] + row[6];
    }

    #pragma unroll
    for (int k = 0; k < 4; k++) {
        const float t  = tv[k];
        const float t4 = t4v[k];
        const float t9 = t9v[k];

        float h[7];
        #pragma unroll
        for (int r = 0; r < 7; r++) {
            const int s_ = (k + r) % 7;      // compile-time after unroll
            float hh = fmaf(t,  a[s_], m[s_]);
            hh       = fmaf(t4, b[s_], hh);
            h[r]     = fmaf(t9, c[s_], hh);
        }
        float acc = fmaf(t,  h[2] + h[4], h[3]);
        acc       = fmaf(t4, h[1] + h[5], acc);
        acc       = fmaf(t9, h[0] + h[6], acc);

        oc[(y0 + ly0 + k) * IMG + (x0 + lx)] = acc * inv[k];

        // Slide: row ly0+7+k replaces the retired slot (k % 7 == k)
        if (k < 3) {
            const float* row = &sm[ly0 + 7 + k][lx];
            m[k] = row[3];
            a[k] = row[2] + row[4];
            b[k] = row[1] + row[5];
            c[k] = row[0] + row[6];
        }
    }
}

extern "C" void kernel_launch(void* const* d_in, const int* in_sizes, int n_in,
                              void* d_out, int out_size)
{
    const float* x     = (const float*)d_in[0];
    const float* sigma = (const float*)d_in[1];
    float*       out   = (float*)d_out;

    dim3 block(32, 8, 1);
    dim3 grid(IMG / TILE, IMG / TILE, 16 * 3);   // 8 x 8 x 48
    AdaptiveGaussianFilter_66675072303489_kernel<<<grid, block>>>(x, sigma, out);
}

// round 3
// speedup vs baseline: 1.0215x; 1.0215x over previous
#include <cuda_runtime.h>
#include <cuda_bf16.h>

#define IMG 256
#define TILE 32
#define HALO 3
#define SW (TILE + 2 * HALO)      // 38
#define SPITCH 40                 // padded pitch, conflict-free

__global__ __launch_bounds__(256, 5)
void AdaptiveGaussianFilter_66675072303489_kernel(
    const float* __restrict__ x,
    const float* __restrict__ sigma,
    float* __restrict__ out)
{
    __shared__ float sm[SW][SPITCH];

    const int ch = blockIdx.z;
    const int x0 = blockIdx.x * TILE;
    const int y0 = blockIdx.y * TILE;

    const float* xc = x     + (size_t)ch * IMG * IMG;
    const float* sc = sigma + (size_t)ch * IMG * IMG;
    float*       oc = out   + (size_t)ch * IMG * IMG;

    const int tid = threadIdx.y * 32 + threadIdx.x;
    const int lx  = threadIdx.x;
    const int ly0 = threadIdx.y * 4;

    // Preload the 4 sigma values (overlap global latency with smem fill)
    float sv[4];
    #pragma unroll
    for (int k = 0; k < 4; k++)
        sv[k] = sc[(y0 + ly0 + k) * IMG + (x0 + lx)];

    // ---- Halo tile fill: fast path for interior blocks (no reflect) ----
    const bool interior = (blockIdx.x != 0) & (blockIdx.x != 7) &
                          (blockIdx.y != 0) & (blockIdx.y != 7);
    if (interior) {
        const float* src = xc + (y0 - HALO) * IMG + (x0 - HALO);
        #pragma unroll
        for (int i = tid; i < SW * SW; i += 256) {
            int sy = i / SW;
            int sx = i - sy * SW;
            sm[sy][sx] = src[sy * IMG + sx];
        }
    } else {
        #pragma unroll
        for (int i = tid; i < SW * SW; i += 256) {
            int sy = i / SW;
            int sx = i - sy * SW;
            int gy = y0 + sy - HALO;
            int gx = x0 + sx - HALO;
            gy = (gy < 0) ? -gy : ((gy > IMG - 1) ? 2 * (IMG - 1) - gy : gy);
            gx = (gx < 0) ? -gx : ((gx > IMG - 1) ? 2 * (IMG - 1) - gx : gx);
            sm[sy][sx] = xc[gy * IMG + gx];
        }
    }
    __syncthreads();

    // ---- Rolling window of t-independent row quartets ----
    // m = w3, a = w2+w4, b = w1+w5, c = w0+w6
    float m[7], a[7], b[7], c[7];
    #pragma unroll
    for (int i = 0; i < 7; i++) {
        const float* row = &sm[ly0 + i][lx];
        m[i] = row[3];
        a[i] = row[2] + row[4];
        b[i] = row[1] + row[5];
        c[i] = row[0] + row[6];
    }

    #pragma unroll
    for (int k = 0; k < 4; k++) {
        // Per-pixel weights from one exp: t = exp(-sigma^2/2)
        float t  = __expf(-0.5f * sv[k] * sv[k]);
        float t2 = t * t;
        float t4 = t2 * t2;
        float t9 = t4 * t4 * t;
        float S  = fmaf(2.0f, t + t4 + t9, 1.0f);

        float h[7];
        #pragma unroll
        for (int r = 0; r < 7; r++) {
            const int s_ = (k + r) % 7;
            float hh = fmaf(t,  a[s_], m[s_]);
            hh       = fmaf(t4, b[s_], hh);
            h[r]     = fmaf(t9, c[s_], hh);
        }
        float acc = fmaf(t,  h[2] + h[4], h[3]);
        acc       = fmaf(t4, h[1] + h[5], acc);
        acc       = fmaf(t9, h[0] + h[6], acc);

        oc[(y0 + ly0 + k) * IMG + (x0 + lx)] = __fdividef(acc, S * S);

        if (k < 3) {
            const float* row = &sm[ly0 + 7 + k][lx];
            m[k] = row[3];
            a[k] = row[2] + row[4];
            b[k] = row[1] + row[5];
            c[k] = row[0] + row[6];
        }
    }
}

extern "C" void kernel_launch(void* const* d_in, const int* in_sizes, int n_in,
                              void* d_out, int out_size)
{
    const float* x     = (const float*)d_in[0];
    const float* sigma = (const float*)d_in[1];
    float*       out   = (float*)d_out;

    dim3 block(32, 8, 1);
    dim3 grid(IMG / TILE, IMG / TILE, 16 * 3);
    AdaptiveGaussianFilter_66675072303489_kernel<<<grid, block>>>(x, sigma, out);
}